// round 6
// baseline (speedup 1.0000x reference)
#include <cuda_runtime.h>
#include <cuda_bf16.h>
#include <stdint.h>

// Problem constants
#define T_SEQ 512
#define BATCH 64
#define DIM   1024
#define LAT   1024
#define NPACK 4096            // 4*LAT, gate-interleaved packed columns: p = 4*j + g
#define M1    32768           // T_SEQ*BATCH

// ---------------------------------------------------------------------------
// Device scratch (static __device__ arrays; no allocations anywhere)
// ---------------------------------------------------------------------------
__device__ float          g_gx[134217728];          // [M1][NPACK] fp32 x-part gates (512 MB)
__device__ __nv_bfloat16  g_Wxh[4194304], g_Wxl[4194304];  // Wx packed [NPACK][DIM] hi/lo
__device__ __nv_bfloat16  g_Whh[4194304], g_Whl[4194304];  // Wh packed [NPACK][LAT] hi/lo
__device__ __nv_bfloat16  g_xh[33554432], g_xl[33554432];  // x split   [M1][DIM]    hi/lo
__device__ __nv_bfloat16  g_hh[2][65536], g_hl[2][65536];  // h state double-buffered, bf16 hi/lo
__device__ float          g_c[65536];                       // c state fp32
__device__ float          g_bias[4096];                     // packed bias

// ---------------------------------------------------------------------------
// mma.sync m16n8k16 bf16 helper (fp32 accumulate)
// ---------------------------------------------------------------------------
__device__ __forceinline__ void mma_bf16(float c[4], const uint32_t a[4], const uint32_t b[2]) {
    asm volatile(
        "mma.sync.aligned.m16n8k16.row.col.f32.bf16.bf16.f32 "
        "{%0,%1,%2,%3}, {%4,%5,%6,%7}, {%8,%9}, {%0,%1,%2,%3};\n"
        : "+f"(c[0]), "+f"(c[1]), "+f"(c[2]), "+f"(c[3])
        : "r"(a[0]), "r"(a[1]), "r"(a[2]), "r"(a[3]), "r"(b[0]), "r"(b[1]));
}

// ---------------------------------------------------------------------------
// Prep: transpose + gate-interleave + bf16 hi/lo split of the 4 gate weights.
// Source W_g is [D+L, L] row-major. Dest: n-major [p][k] so GEMM tiles load
// contiguous k rows. p = 4*j + g.
// ---------------------------------------------------------------------------
__global__ void prep_weights(const float* __restrict__ Wf, const float* __restrict__ Wi,
                             const float* __restrict__ Wo, const float* __restrict__ Wg) {
    __shared__ float tile[32][33];
    const int g  = blockIdx.z;
    const float* W = (g == 0) ? Wf : (g == 1) ? Wi : (g == 2) ? Wo : Wg;
    const int k0 = blockIdx.x * 32;     // 0..2047 (k index in D+L)
    const int j0 = blockIdx.y * 32;     // 0..1023
    const int tx = threadIdx.x & 31;
    const int ty = threadIdx.x >> 5;    // 0..7

    for (int r = ty; r < 32; r += 8)
        tile[r][tx] = W[(size_t)(k0 + r) * LAT + (j0 + tx)];
    __syncthreads();

    const bool isx = (k0 < DIM);
    for (int lj = ty; lj < 32; lj += 8) {
        float v = tile[tx][lj];                                   // (k0+tx, j0+lj)
        __nv_bfloat16 hi = __float2bfloat16_rn(v);
        __nv_bfloat16 lo = __float2bfloat16_rn(v - __bfloat162float(hi));
        int p = 4 * (j0 + lj) + g;
        size_t idx = (size_t)p * 1024 + (size_t)(isx ? (k0 + tx) : (k0 + tx - DIM));
        if (isx) { g_Wxh[idx] = hi; g_Wxl[idx] = lo; }
        else     { g_Whh[idx] = hi; g_Whl[idx] = lo; }
    }
}

// Pack bias into gate-interleaved order; zero initial h (buffer 0) and c.
__global__ void pack_bias_zero(const float* __restrict__ bf, const float* __restrict__ bi,
                               const float* __restrict__ bo, const float* __restrict__ bg) {
    int i = blockIdx.x * blockDim.x + threadIdx.x;   // 65536 threads
    if (i < 4096) {
        int gs = i & 3, j = i >> 2;
        const float* b = (gs == 0) ? bf : (gs == 1) ? bi : (gs == 2) ? bo : bg;
        g_bias[i] = b[j];
    }
    if (i < 65536) {
        g_c[i]     = 0.0f;
        g_hh[0][i] = __float2bfloat16_rn(0.0f);
        g_hl[0][i] = __float2bfloat16_rn(0.0f);
    }
}

// Split x into bf16 hi/lo.
__global__ void split_x(const float* __restrict__ x) {
    size_t stride = (size_t)gridDim.x * blockDim.x;
    for (size_t i = (size_t)blockIdx.x * blockDim.x + threadIdx.x; i < 33554432u; i += stride) {
        float v = x[i];
        __nv_bfloat16 hi = __float2bfloat16_rn(v);
        g_xh[i] = hi;
        g_xl[i] = __float2bfloat16_rn(v - __bfloat162float(hi));
    }
}

// ---------------------------------------------------------------------------
// GEMM1: gates_x[M1, NPACK] = x[M1, DIM] @ Wx_packed[DIM, NPACK]
// 3xbf16 error-compensated: C = Ah*Bh + Ah*Bl + Al*Bh, fp32 accum.
// CTA tile 128x128, BK=32, 256 threads / 8 warps (2m x 4n), warp tile 64x32.
// ---------------------------------------------------------------------------
__global__ __launch_bounds__(256) void gemm_x() {
    __shared__ __align__(16) __nv_bfloat16 Ash[128][40], Asl[128][40];
    __shared__ __align__(16) __nv_bfloat16 Bsh[128][40], Bsl[128][40];

    const int bm = blockIdx.x >> 5;          // 0..255
    const int bn = blockIdx.x & 31;          // 0..31   (n fastest: B tiles stay L2-hot)
    const size_t gm0 = (size_t)bm * 128;
    const size_t gn0 = (size_t)bn * 128;

    const int lane = threadIdx.x & 31, wid = threadIdx.x >> 5;
    const int wm = wid >> 2, wn = wid & 3;
    const int gid = lane >> 2, tig = lane & 3;

    float C[4][4][4];
    #pragma unroll
    for (int a = 0; a < 4; ++a)
        #pragma unroll
        for (int b = 0; b < 4; ++b)
            #pragma unroll
            for (int c = 0; c < 4; ++c) C[a][b][c] = 0.0f;

    for (int it = 0; it < 32; ++it) {
        const int k0 = it * 32;
        // cooperative tile loads: 512 uint4 slots per array (128 rows x 4)
        #pragma unroll
        for (int s = threadIdx.x; s < 512; s += 256) {
            int r = s >> 2, q = (s & 3) * 8;   // q in bf16 units {0,8,16,24}
            *(uint4*)&Ash[r][q] = *(const uint4*)(g_xh  + (gm0 + r) * 1024 + k0 + q);
            *(uint4*)&Asl[r][q] = *(const uint4*)(g_xl  + (gm0 + r) * 1024 + k0 + q);
            *(uint4*)&Bsh[r][q] = *(const uint4*)(g_Wxh + (gn0 + r) * 1024 + k0 + q);
            *(uint4*)&Bsl[r][q] = *(const uint4*)(g_Wxl + (gn0 + r) * 1024 + k0 + q);
        }
        __syncthreads();

        #pragma unroll
        for (int kk = 0; kk < 32; kk += 16) {
            const int cb = kk + 2 * tig;
            uint32_t ah[4][4], al[4][4], bh[4][2], bl[4][2];
            #pragma unroll
            for (int mt = 0; mt < 4; ++mt) {
                int row = wm * 64 + mt * 16 + gid;
                ah[mt][0] = *(const uint32_t*)&Ash[row    ][cb    ];
                ah[mt][1] = *(const uint32_t*)&Ash[row + 8][cb    ];
                ah[mt][2] = *(const uint32_t*)&Ash[row    ][cb + 8];
                ah[mt][3] = *(const uint32_t*)&Ash[row + 8][cb + 8];
                al[mt][0] = *(const uint32_t*)&Asl[row    ][cb    ];
                al[mt][1] = *(const uint32_t*)&Asl[row + 8][cb    ];
                al[mt][2] = *(const uint32_t*)&Asl[row    ][cb + 8];
                al[mt][3] = *(const uint32_t*)&Asl[row + 8][cb + 8];
            }
            #pragma unroll
            for (int nt = 0; nt < 4; ++nt) {
                int nr = wn * 32 + nt * 8 + gid;
                bh[nt][0] = *(const uint32_t*)&Bsh[nr][cb    ];
                bh[nt][1] = *(const uint32_t*)&Bsh[nr][cb + 8];
                bl[nt][0] = *(const uint32_t*)&Bsl[nr][cb    ];
                bl[nt][1] = *(const uint32_t*)&Bsl[nr][cb + 8];
            }
            #pragma unroll
            for (int mt = 0; mt < 4; ++mt)
                #pragma unroll
                for (int nt = 0; nt < 4; ++nt) {
                    mma_bf16(C[mt][nt], ah[mt], bh[nt]);
                    mma_bf16(C[mt][nt], ah[mt], bl[nt]);
                    mma_bf16(C[mt][nt], al[mt], bh[nt]);
                }
        }
        __syncthreads();
    }

    // store C -> g_gx (fp32)
    #pragma unroll
    for (int mt = 0; mt < 4; ++mt)
        #pragma unroll
        for (int nt = 0; nt < 4; ++nt) {
            size_t row = gm0 + wm * 64 + mt * 16 + gid;
            size_t col = gn0 + wn * 32 + nt * 8 + 2 * tig;
            *(float2*)&g_gx[row * 4096 + col]       = make_float2(C[mt][nt][0], C[mt][nt][1]);
            *(float2*)&g_gx[(row + 8) * 4096 + col] = make_float2(C[mt][nt][2], C[mt][nt][3]);
        }
}

// ---------------------------------------------------------------------------
// Per-step recurrent kernel: gates = gates_x[t] + h_{t-1} @ Wh_packed + bias,
// fused cell update in the epilogue. 128 CTAs (8 latent each), 256 threads.
// h double-buffered (read t&1, write (t&1)^1) -> no cross-CTA race.
// ---------------------------------------------------------------------------
__device__ __forceinline__ void lstm_update(int t, int r, int j,
                                            float pf, float pi, float po, float pg,
                                            int wb, float* __restrict__ out) {
    float f  = 1.0f / (1.0f + __expf(-pf));
    float ii = 1.0f / (1.0f + __expf(-pi));
    float o  = 1.0f / (1.0f + __expf(-po));
    float gg = tanhf(pg);
    int idx  = r * 1024 + j;
    float cn = f * g_c[idx] + ii * gg;
    g_c[idx] = cn;
    float h  = o * tanhf(cn);
    out[(size_t)t * 65536 + idx] = h;
    __nv_bfloat16 hi = __float2bfloat16_rn(h);
    g_hh[wb][idx] = hi;
    g_hl[wb][idx] = __float2bfloat16_rn(h - __bfloat162float(hi));
}

__global__ __launch_bounds__(256) void lstm_step(int t, float* __restrict__ out) {
    __shared__ __align__(16) __nv_bfloat16 sAh[64][72], sAl[64][72];
    __shared__ __align__(16) __nv_bfloat16 sBh[32][72], sBl[32][72];

    const int nt = blockIdx.x;          // 0..127
    const int P0 = nt * 32;             // packed col base
    const int rb = t & 1, wb = rb ^ 1;
    const __nv_bfloat16* __restrict__ hh = g_hh[rb];
    const __nv_bfloat16* __restrict__ hl = g_hl[rb];
    const float* __restrict__ gx = g_gx + (size_t)t * BATCH * 4096;

    const int lane = threadIdx.x & 31, wid = threadIdx.x >> 5;
    const int mt = wid & 3, nh = wid >> 2;      // warp tile: rows 16*mt, cols 16*nh
    const int gid = lane >> 2, tig = lane & 3;

    float C[2][4] = {};

    for (int it = 0; it < 16; ++it) {
        const int k0 = it * 64;
        #pragma unroll
        for (int s = threadIdx.x; s < 512; s += 256) {   // A: 64 rows x 8 uint4
            int r = s >> 3, q = (s & 7) * 8;
            *(uint4*)&sAh[r][q] = *(const uint4*)(hh + r * 1024 + k0 + q);
            *(uint4*)&sAl[r][q] = *(const uint4*)(hl + r * 1024 + k0 + q);
        }
        {                                                 // B: 32 rows x 8 uint4 = 256 slots
            int s = threadIdx.x;
            int r = s >> 3, q = (s & 7) * 8;
            size_t base = (size_t)(P0 + r) * 1024 + k0 + q;
            *(uint4*)&sBh[r][q] = *(const uint4*)(g_Whh + base);
            *(uint4*)&sBl[r][q] = *(const uint4*)(g_Whl + base);
        }
        __syncthreads();

        #pragma unroll
        for (int kk = 0; kk < 64; kk += 16) {
            const int cb = kk + 2 * tig;
            const int row = mt * 16 + gid;
            uint32_t ah[4], al[4];
            ah[0] = *(const uint32_t*)&sAh[row    ][cb    ];
            ah[1] = *(const uint32_t*)&sAh[row + 8][cb    ];
            ah[2] = *(const uint32_t*)&sAh[row    ][cb + 8];
            ah[3] = *(const uint32_t*)&sAh[row + 8][cb + 8];
            al[0] = *(const uint32_t*)&sAl[row    ][cb    ];
            al[1] = *(const uint32_t*)&sAl[row + 8][cb    ];
            al[2] = *(const uint32_t*)&sAl[row    ][cb + 8];
            al[3] = *(const uint32_t*)&sAl[row + 8][cb + 8];
            #pragma unroll
            for (int nb = 0; nb < 2; ++nb) {
                int nr = nh * 16 + nb * 8 + gid;
                uint32_t bh[2], bl[2];
                bh[0] = *(const uint32_t*)&sBh[nr][cb    ];
                bh[1] = *(const uint32_t*)&sBh[nr][cb + 8];
                bl[0] = *(const uint32_t*)&sBl[nr][cb    ];
                bl[1] = *(const uint32_t*)&sBl[nr][cb + 8];
                mma_bf16(C[nb], ah, bh);
                mma_bf16(C[nb], ah, bl);
                mma_bf16(C[nb], al, bh);
            }
        }
        __syncthreads();
    }

    // Epilogue: add x-part + bias, exchange (o,g)<->(f,i) within lane pairs, update cell.
    const int row = mt * 16 + gid;
    #pragma unroll
    for (int nb = 0; nb < 2; ++nb) {
        int colb = nh * 16 + nb * 8 + 2 * tig;
        int p = P0 + colb;                       // even; p%4==0 -> (f,i), p%4==2 -> (o,g)
        float v0 = C[nb][0] + gx[(size_t)row * 4096 + p]       + g_bias[p];
        float v1 = C[nb][1] + gx[(size_t)row * 4096 + p + 1]   + g_bias[p + 1];
        float v2 = C[nb][2] + gx[(size_t)(row + 8) * 4096 + p]     + g_bias[p];
        float v3 = C[nb][3] + gx[(size_t)(row + 8) * 4096 + p + 1] + g_bias[p + 1];
        float q0 = __shfl_xor_sync(0xffffffffu, v0, 1);
        float q1 = __shfl_xor_sync(0xffffffffu, v1, 1);
        float q2 = __shfl_xor_sync(0xffffffffu, v2, 1);
        float q3 = __shfl_xor_sync(0xffffffffu, v3, 1);
        if ((lane & 1) == 0) {                   // this lane holds (f,i); partner held (o,g)
            int j = p >> 2;
            lstm_update(t, row,     j, v0, v1, q0, q1, wb, out);
            lstm_update(t, row + 8, j, v2, v3, q2, q3, wb, out);
        }
    }
}

// ---------------------------------------------------------------------------
// Launch: all on the (per-thread) default stream -> serialized, capturable.
// ---------------------------------------------------------------------------
extern "C" void kernel_launch(void* const* d_in, const int* in_sizes, int n_in,
                              void* d_out, int out_size) {
    const float* x  = (const float*)d_in[0];
    const float* Wf = (const float*)d_in[1];
    const float* bf = (const float*)d_in[2];
    const float* Wi = (const float*)d_in[3];
    const float* bi = (const float*)d_in[4];
    const float* Wo = (const float*)d_in[5];
    const float* bo = (const float*)d_in[6];
    const float* Wg = (const float*)d_in[7];
    const float* bg = (const float*)d_in[8];
    float* out = (float*)d_out;

    prep_weights<<<dim3(64, 32, 4), 256>>>(Wf, Wi, Wo, Wg);
    pack_bias_zero<<<256, 256>>>(bf, bi, bo, bg);
    split_x<<<8192, 256>>>(x);
    gemm_x<<<8192, 256>>>();
    for (int t = 0; t < T_SEQ; ++t)
        lstm_step<<<128, 256>>>(t, out);
}

// round 8
// speedup vs baseline: 1.6756x; 1.6756x over previous
#include <cuda_runtime.h>
#include <cuda_bf16.h>
#include <stdint.h>

// Problem constants
#define T_SEQ 512
#define BATCH 64
#define DIM   1024
#define LAT   1024
#define NPACK 4096            // 4*LAT, gate-interleaved packed columns: p = 4*j + g
#define M1    32768           // T_SEQ*BATCH
#define NCTA  128             // persistent grid (<=148 SMs, 1 CTA/SM by smem)

// ---------------------------------------------------------------------------
// Device scratch (static __device__ arrays; no allocations anywhere)
// ---------------------------------------------------------------------------
__device__ float          g_gx[134217728];          // [M1][NPACK] fp32 x-part gates (512 MB)
__device__ __nv_bfloat16  g_Wxh[4194304], g_Wxl[4194304];  // Wx packed [NPACK][DIM] hi/lo
__device__ __nv_bfloat16  g_Whh[4194304], g_Whl[4194304];  // Wh packed [NPACK][LAT] hi/lo
__device__ __nv_bfloat16  g_xh[33554432], g_xl[33554432];  // x split   [M1][DIM]    hi/lo
__device__ __nv_bfloat16  g_hh[2][65536], g_hl[2][65536];  // h state double-buffered, bf16 hi/lo
__device__ float          g_c[65536];                       // c state fp32
__device__ float          g_bias[4096];                     // packed bias
__device__ unsigned       g_bar_count;                      // grid barrier
__device__ unsigned       g_bar_phase;

// ---------------------------------------------------------------------------
// mma.sync m16n8k16 bf16 helper (fp32 accumulate)
// ---------------------------------------------------------------------------
__device__ __forceinline__ void mma_bf16(float c[4], const uint32_t a[4], const uint32_t b[2]) {
    asm volatile(
        "mma.sync.aligned.m16n8k16.row.col.f32.bf16.bf16.f32 "
        "{%0,%1,%2,%3}, {%4,%5,%6,%7}, {%8,%9}, {%0,%1,%2,%3};\n"
        : "+f"(c[0]), "+f"(c[1]), "+f"(c[2]), "+f"(c[3])
        : "r"(a[0]), "r"(a[1]), "r"(a[2]), "r"(a[3]), "r"(b[0]), "r"(b[1]));
}

// cp.async helpers (16B, L2-only path: .cg)
__device__ __forceinline__ void cp_async16(void* sptr, const void* gptr) {
    uint32_t s = (uint32_t)__cvta_generic_to_shared(sptr);
    asm volatile("cp.async.cg.shared.global [%0], [%1], 16;\n" :: "r"(s), "l"(gptr));
}
__device__ __forceinline__ void cp_commit() { asm volatile("cp.async.commit_group;\n"); }
__device__ __forceinline__ void cp_wait1()  { asm volatile("cp.async.wait_group 1;\n"); }
__device__ __forceinline__ void cp_wait0()  { asm volatile("cp.async.wait_group 0;\n"); }

// ---------------------------------------------------------------------------
// Prep: transpose + gate-interleave + bf16 hi/lo split of the 4 gate weights.
// Source W_g is [D+L, L] row-major. Dest: n-major [p][k]. p = 4*j + g.
// ---------------------------------------------------------------------------
__global__ void prep_weights(const float* __restrict__ Wf, const float* __restrict__ Wi,
                             const float* __restrict__ Wo, const float* __restrict__ Wg) {
    __shared__ float tile[32][33];
    const int g  = blockIdx.z;
    const float* W = (g == 0) ? Wf : (g == 1) ? Wi : (g == 2) ? Wo : Wg;
    const int k0 = blockIdx.x * 32;     // 0..2047 (k index in D+L)
    const int j0 = blockIdx.y * 32;     // 0..1023
    const int tx = threadIdx.x & 31;
    const int ty = threadIdx.x >> 5;    // 0..7

    for (int r = ty; r < 32; r += 8)
        tile[r][tx] = W[(size_t)(k0 + r) * LAT + (j0 + tx)];
    __syncthreads();

    const bool isx = (k0 < DIM);
    for (int lj = ty; lj < 32; lj += 8) {
        float v = tile[tx][lj];                                   // (k0+tx, j0+lj)
        __nv_bfloat16 hi = __float2bfloat16_rn(v);
        __nv_bfloat16 lo = __float2bfloat16_rn(v - __bfloat162float(hi));
        int p = 4 * (j0 + lj) + g;
        size_t idx = (size_t)p * 1024 + (size_t)(isx ? (k0 + tx) : (k0 + tx - DIM));
        if (isx) { g_Wxh[idx] = hi; g_Wxl[idx] = lo; }
        else     { g_Whh[idx] = hi; g_Whl[idx] = lo; }
    }
}

// Pack bias gate-interleaved; zero initial h (buffer 0) and c; reset barrier.
__global__ void pack_bias_zero(const float* __restrict__ bf, const float* __restrict__ bi,
                               const float* __restrict__ bo, const float* __restrict__ bg) {
    int i = blockIdx.x * blockDim.x + threadIdx.x;   // 65536 threads
    if (i == 0) { g_bar_count = 0; g_bar_phase = 0; }
    if (i < 4096) {
        int gs = i & 3, j = i >> 2;
        const float* b = (gs == 0) ? bf : (gs == 1) ? bi : (gs == 2) ? bo : bg;
        g_bias[i] = b[j];
    }
    if (i < 65536) {
        g_c[i]     = 0.0f;
        g_hh[0][i] = __float2bfloat16_rn(0.0f);
        g_hl[0][i] = __float2bfloat16_rn(0.0f);
    }
}

// Split x into bf16 hi/lo.
__global__ void split_x(const float* __restrict__ x) {
    size_t stride = (size_t)gridDim.x * blockDim.x;
    for (size_t i = (size_t)blockIdx.x * blockDim.x + threadIdx.x; i < 33554432u; i += stride) {
        float v = x[i];
        __nv_bfloat16 hi = __float2bfloat16_rn(v);
        g_xh[i] = hi;
        g_xl[i] = __float2bfloat16_rn(v - __bfloat162float(hi));
    }
}

// ---------------------------------------------------------------------------
// GEMM1: gates_x[M1, NPACK] = x[M1, DIM] @ Wx_packed[DIM, NPACK]
// 3xbf16 error-compensated: C = Ah*Bh + Ah*Bl + Al*Bh, fp32 accum.
// CTA tile 128x128, BK=32, 256 threads / 8 warps (2m x 4n), warp tile 64x32.
// 2-stage cp.async pipeline (dynamic smem, 80 KB/CTA).
// ---------------------------------------------------------------------------
typedef __nv_bfloat16 GTile[128][40];     // 10240 B
#define GEMM_SMEM 81920                   // 8 tiles (4 arrays x 2 stages)

__global__ __launch_bounds__(256) void gemm_x() {
    extern __shared__ __align__(16) unsigned char gsm[];
    GTile* Ash = (GTile*)(gsm);               // [2]
    GTile* Asl = (GTile*)(gsm + 20480);       // [2]
    GTile* Bsh = (GTile*)(gsm + 40960);       // [2]
    GTile* Bsl = (GTile*)(gsm + 61440);       // [2]

    const int bm = blockIdx.x >> 5;          // 0..255
    const int bn = blockIdx.x & 31;          // 0..31   (n fastest: B tiles stay L2-hot)
    const size_t gm0 = (size_t)bm * 128;
    const size_t gn0 = (size_t)bn * 128;

    const int lane = threadIdx.x & 31, wid = threadIdx.x >> 5;
    const int wm = wid >> 2, wn = wid & 3;
    const int gid = lane >> 2, tig = lane & 3;

    float C[4][4][4];
    #pragma unroll
    for (int a = 0; a < 4; ++a)
        #pragma unroll
        for (int b = 0; b < 4; ++b)
            #pragma unroll
            for (int c = 0; c < 4; ++c) C[a][b][c] = 0.0f;

    // stage-load: issue cp.async for K-slab `it` into stage `st`
    auto load_slab = [&](int st, int it) {
        const int k0 = it * 32;
        #pragma unroll
        for (int s = threadIdx.x; s < 512; s += 256) {
            int r = s >> 2, q = (s & 3) * 8;
            cp_async16(&Ash[st][r][q], g_xh  + (gm0 + r) * 1024 + k0 + q);
            cp_async16(&Asl[st][r][q], g_xl  + (gm0 + r) * 1024 + k0 + q);
            cp_async16(&Bsh[st][r][q], g_Wxh + (gn0 + r) * 1024 + k0 + q);
            cp_async16(&Bsl[st][r][q], g_Wxl + (gn0 + r) * 1024 + k0 + q);
        }
        cp_commit();
    };

    load_slab(0, 0);

    for (int it = 0; it < 32; ++it) {
        const int b = it & 1;
        if (it < 31) { load_slab(b ^ 1, it + 1); cp_wait1(); }
        else         { cp_wait0(); }
        __syncthreads();

        #pragma unroll
        for (int kk = 0; kk < 32; kk += 16) {
            const int cb = kk + 2 * tig;
            uint32_t ah[4][4], al[4][4], bh[4][2], bl[4][2];
            #pragma unroll
            for (int mt = 0; mt < 4; ++mt) {
                int row = wm * 64 + mt * 16 + gid;
                ah[mt][0] = *(const uint32_t*)&Ash[b][row    ][cb    ];
                ah[mt][1] = *(const uint32_t*)&Ash[b][row + 8][cb    ];
                ah[mt][2] = *(const uint32_t*)&Ash[b][row    ][cb + 8];
                ah[mt][3] = *(const uint32_t*)&Ash[b][row + 8][cb + 8];
                al[mt][0] = *(const uint32_t*)&Asl[b][row    ][cb    ];
                al[mt][1] = *(const uint32_t*)&Asl[b][row + 8][cb    ];
                al[mt][2] = *(const uint32_t*)&Asl[b][row    ][cb + 8];
                al[mt][3] = *(const uint32_t*)&Asl[b][row + 8][cb + 8];
            }
            #pragma unroll
            for (int nt = 0; nt < 4; ++nt) {
                int nr = wn * 32 + nt * 8 + gid;
                bh[nt][0] = *(const uint32_t*)&Bsh[b][nr][cb    ];
                bh[nt][1] = *(const uint32_t*)&Bsh[b][nr][cb + 8];
                bl[nt][0] = *(const uint32_t*)&Bsl[b][nr][cb    ];
                bl[nt][1] = *(const uint32_t*)&Bsl[b][nr][cb + 8];
            }
            #pragma unroll
            for (int mt = 0; mt < 4; ++mt)
                #pragma unroll
                for (int nt = 0; nt < 4; ++nt) {
                    mma_bf16(C[mt][nt], ah[mt], bh[nt]);
                    mma_bf16(C[mt][nt], ah[mt], bl[nt]);
                    mma_bf16(C[mt][nt], al[mt], bh[nt]);
                }
        }
        __syncthreads();
    }

    #pragma unroll
    for (int mt = 0; mt < 4; ++mt)
        #pragma unroll
        for (int nt = 0; nt < 4; ++nt) {
            size_t row = gm0 + wm * 64 + mt * 16 + gid;
            size_t col = gn0 + wn * 32 + nt * 8 + 2 * tig;
            *(float2*)&g_gx[row * 4096 + col]       = make_float2(C[mt][nt][0], C[mt][nt][1]);
            *(float2*)&g_gx[(row + 8) * 4096 + col] = make_float2(C[mt][nt][2], C[mt][nt][3]);
        }
}

// ---------------------------------------------------------------------------
// Persistent recurrent kernel: all 512 steps in one launch.
// 128 CTAs x 256 thr; each CTA owns 32 packed cols (8 latent j), weights
// resident in smem; h streamed per-step via cp.async double buffer; one
// sense-reversing grid barrier per step (h double-buffered).
// ---------------------------------------------------------------------------
struct SmemLayout {
    __nv_bfloat16 Wh[32][1032];     // padded stride: conflict-free frags
    __nv_bfloat16 Wl[32][1032];
    __nv_bfloat16 Ah[2][64][136];   // K-chunk 128, double buffered
    __nv_bfloat16 Al[2][64][136];
};
#define SMEM_BYTES sizeof(SmemLayout)   // 201728 B

__device__ __forceinline__ void grid_bar(unsigned target) {
    __syncthreads();
    if (threadIdx.x == 0) {
        __threadfence();
        unsigned prev = atomicAdd(&g_bar_count, 1);
        if (prev == NCTA - 1) {
            g_bar_count = 0;
            __threadfence();
            atomicAdd(&g_bar_phase, 1);
        } else {
            unsigned p;
            do {
                asm volatile("ld.acquire.gpu.global.u32 %0, [%1];"
                             : "=r"(p) : "l"(&g_bar_phase));
            } while (p < target);
        }
    }
    __syncthreads();
}

__device__ __forceinline__ void lstm_update(int t, int r, int j,
                                            float pf, float pi, float po, float pg,
                                            int wb, float* __restrict__ out) {
    float f  = 1.0f / (1.0f + __expf(-pf));
    float ii = 1.0f / (1.0f + __expf(-pi));
    float o  = 1.0f / (1.0f + __expf(-po));
    float gg = tanhf(pg);
    int idx  = r * 1024 + j;
    float cn = f * g_c[idx] + ii * gg;
    g_c[idx] = cn;
    float h  = o * tanhf(cn);
    out[(size_t)t * 65536 + idx] = h;
    __nv_bfloat16 hi = __float2bfloat16_rn(h);
    g_hh[wb][idx] = hi;
    g_hl[wb][idx] = __float2bfloat16_rn(h - __bfloat162float(hi));
}

__global__ __launch_bounds__(256, 1) void lstm_persist(float* __restrict__ out) {
    extern __shared__ __align__(16) unsigned char smem_raw[];
    SmemLayout& S = *reinterpret_cast<SmemLayout*>(smem_raw);

    const int tid  = threadIdx.x;
    const int lane = tid & 31, wid = tid >> 5;
    const int mt = wid & 3, nh = wid >> 2;       // warp tile: rows 16*mt, cols 16*nh
    const int g8  = lane >> 2, tig = lane & 3;
    const int P0  = blockIdx.x * 32;
    const int row = mt * 16 + g8;

    // One-time weight slice load: 32 rows x 1024 k, hi+lo (128 KB) into smem.
    for (int s = tid; s < 4096; s += 256) {
        int r = s >> 7, q = (s & 127) * 8;
        *(uint4*)&S.Wh[r][q] = *(const uint4*)(g_Whh + (size_t)(P0 + r) * 1024 + q);
        *(uint4*)&S.Wl[r][q] = *(const uint4*)(g_Whl + (size_t)(P0 + r) * 1024 + q);
    }
    __syncthreads();

    // Loop-invariant: packed columns + bias for this thread's epilogue.
    int pcol[2];  float vb[2][2];
    #pragma unroll
    for (int nb = 0; nb < 2; ++nb) {
        pcol[nb] = P0 + nh * 16 + nb * 8 + 2 * tig;
        vb[nb][0] = g_bias[pcol[nb]];
        vb[nb][1] = g_bias[pcol[nb] + 1];
    }

    for (int t = 0; t < T_SEQ; ++t) {
        const int rb = t & 1, wb = rb ^ 1;
        const __nv_bfloat16* __restrict__ hh = g_hh[rb];
        const __nv_bfloat16* __restrict__ hl = g_hl[rb];
        const float* __restrict__ gx = g_gx + (size_t)t * BATCH * 4096;

        // Prefetch this thread's gates_x operands (streaming; hidden by compute).
        float2 vg[2][2];
        #pragma unroll
        for (int nb = 0; nb < 2; ++nb) {
            int p = pcol[nb];
            vg[nb][0] = __ldcs((const float2*)&gx[(size_t)row * 4096 + p]);
            vg[nb][1] = __ldcs((const float2*)&gx[(size_t)(row + 8) * 4096 + p]);
        }

        float C[2][4] = {};

        // Preload chunk 0 of h (hi+lo).
        for (int s = tid; s < 1024; s += 256) {
            int r = s >> 4, q = (s & 15) * 8;
            cp_async16(&S.Ah[0][r][q], hh + r * 1024 + q);
            cp_async16(&S.Al[0][r][q], hl + r * 1024 + q);
        }
        cp_commit();

        for (int it = 0; it < 8; ++it) {
            if (it < 7) {
                const int k0 = (it + 1) * 128, b = (it + 1) & 1;
                for (int s = tid; s < 1024; s += 256) {
                    int r = s >> 4, q = (s & 15) * 8;
                    cp_async16(&S.Ah[b][r][q], hh + r * 1024 + k0 + q);
                    cp_async16(&S.Al[b][r][q], hl + r * 1024 + k0 + q);
                }
                cp_commit();
                cp_wait1();
            } else {
                cp_wait0();
            }
            __syncthreads();
            const int b = it & 1;
            #pragma unroll
            for (int kk = 0; kk < 128; kk += 16) {
                const int ca = kk + 2 * tig;          // k within chunk (A)
                const int cw = it * 128 + ca;         // global k (W, fully resident)
                uint32_t ah[4], al[4];
                ah[0] = *(const uint32_t*)&S.Ah[b][row    ][ca    ];
                ah[1] = *(const uint32_t*)&S.Ah[b][row + 8][ca    ];
                ah[2] = *(const uint32_t*)&S.Ah[b][row    ][ca + 8];
                ah[3] = *(const uint32_t*)&S.Ah[b][row + 8][ca + 8];
                al[0] = *(const uint32_t*)&S.Al[b][row    ][ca    ];
                al[1] = *(const uint32_t*)&S.Al[b][row + 8][ca    ];
                al[2] = *(const uint32_t*)&S.Al[b][row    ][ca + 8];
                al[3] = *(const uint32_t*)&S.Al[b][row + 8][ca + 8];
                #pragma unroll
                for (int nb = 0; nb < 2; ++nb) {
                    const int nr = nh * 16 + nb * 8 + g8;
                    uint32_t bh[2], bl[2];
                    bh[0] = *(const uint32_t*)&S.Wh[nr][cw    ];
                    bh[1] = *(const uint32_t*)&S.Wh[nr][cw + 8];
                    bl[0] = *(const uint32_t*)&S.Wl[nr][cw    ];
                    bl[1] = *(const uint32_t*)&S.Wl[nr][cw + 8];
                    mma_bf16(C[nb], ah, bh);
                    mma_bf16(C[nb], ah, bl);
                    mma_bf16(C[nb], al, bh);
                }
            }
            __syncthreads();
        }

        // Epilogue: add x-part + bias, pair-exchange (f,i)<->(o,g), update cell.
        #pragma unroll
        for (int nb = 0; nb < 2; ++nb) {
            float v0 = C[nb][0] + vg[nb][0].x + vb[nb][0];
            float v1 = C[nb][1] + vg[nb][0].y + vb[nb][1];
            float v2 = C[nb][2] + vg[nb][1].x + vb[nb][0];
            float v3 = C[nb][3] + vg[nb][1].y + vb[nb][1];
            float q0 = __shfl_xor_sync(0xffffffffu, v0, 1);
            float q1 = __shfl_xor_sync(0xffffffffu, v1, 1);
            float q2 = __shfl_xor_sync(0xffffffffu, v2, 1);
            float q3 = __shfl_xor_sync(0xffffffffu, v3, 1);
            if ((lane & 1) == 0) {               // holds (f,i); partner held (o,g)
                int j = pcol[nb] >> 2;
                lstm_update(t, row,     j, v0, v1, q0, q1, wb, out);
                lstm_update(t, row + 8, j, v2, v3, q2, q3, wb, out);
            }
        }

        grid_bar((unsigned)(t + 1));
    }
}

// ---------------------------------------------------------------------------
// Launch: default stream, fully capturable; one persistent recurrent kernel.
// ---------------------------------------------------------------------------
extern "C" void kernel_launch(void* const* d_in, const int* in_sizes, int n_in,
                              void* d_out, int out_size) {
    const float* x  = (const float*)d_in[0];
    const float* Wf = (const float*)d_in[1];
    const float* bf = (const float*)d_in[2];
    const float* Wi = (const float*)d_in[3];
    const float* bi = (const float*)d_in[4];
    const float* Wo = (const float*)d_in[5];
    const float* bo = (const float*)d_in[6];
    const float* Wg = (const float*)d_in[7];
    const float* bg = (const float*)d_in[8];
    float* out = (float*)d_out;

    cudaFuncSetAttribute(gemm_x, cudaFuncAttributeMaxDynamicSharedMemorySize,
                         GEMM_SMEM);
    cudaFuncSetAttribute(lstm_persist, cudaFuncAttributeMaxDynamicSharedMemorySize,
                         (int)SMEM_BYTES);

    prep_weights<<<dim3(64, 32, 4), 256>>>(Wf, Wi, Wo, Wg);
    pack_bias_zero<<<256, 256>>>(bf, bi, bo, bg);
    split_x<<<8192, 256>>>(x);
    gemm_x<<<8192, 256, GEMM_SMEM>>>();
    lstm_persist<<<NCTA, 256, SMEM_BYTES>>>(out);
}